// round 3
// baseline (speedup 1.0000x reference)
#include <cuda_runtime.h>
#include <cuda_bf16.h>

// Inputs (metadata order):
//   d_in[0]: pre     float32  [N, 3]   (log-softmax)
//   d_in[1]: y_true  int32    [N]
//   d_in[2]: weight  float32  scalar
// Output: float32 scalar = -sum(w_i * pre[i, y_i]) / N,
//   w_i = weight if |argmax(pre_i) - y_i| == 2 else 1.

#define NBLOCKS 2048
#define NTHREADS 256

__device__ float g_partials[NBLOCKS];
__device__ unsigned int g_done_count;   // static zero-init; reset by last block

__device__ __forceinline__ float row_term(float a, float b, float c, int yt, float w) {
    // argmax with first-occurrence tie-breaking (strict >)
    int pred = 0;
    float best = a;
    if (b > best) { best = b; pred = 1; }
    if (c > best) { pred = 2; }
    float picked = (yt == 0) ? a : ((yt == 1) ? b : c);
    int d = pred - yt;
    bool penal = (d == 2) || (d == -2);
    return penal ? (w * picked) : picked;
}

__global__ void __launch_bounds__(NTHREADS)
nll_fused_kernel(const float* __restrict__ pre,
                 const int* __restrict__ y,
                 const float* __restrict__ wp,
                 float* __restrict__ out,
                 int n, float inv_n_neg) {
    const float4* p4 = reinterpret_cast<const float4*>(pre);
    const int4*   y4 = reinterpret_cast<const int4*>(y);
    const float w = *wp;

    const int nquad  = n >> 2;               // rows processed 4 at a time
    const int stride = gridDim.x * blockDim.x;

    float acc = 0.0f;

    // grid covers nquad exactly when n = 2048*256*4*4; unroll 4 batches 16 LDG.128
    #pragma unroll 4
    for (int q = blockIdx.x * blockDim.x + threadIdx.x; q < nquad; q += stride) {
        float4 f0 = p4[3 * q + 0];
        float4 f1 = p4[3 * q + 1];
        float4 f2 = p4[3 * q + 2];
        int4   yv = y4[q];

        acc += row_term(f0.x, f0.y, f0.z, yv.x, w);
        acc += row_term(f0.w, f1.x, f1.y, yv.y, w);
        acc += row_term(f1.z, f1.w, f2.x, yv.z, w);
        acc += row_term(f2.y, f2.z, f2.w, yv.w, w);
    }

    // scalar tail (empty for this problem's N, kept for generality)
    for (int i = (nquad << 2) + blockIdx.x * blockDim.x + threadIdx.x; i < n; i += stride) {
        acc += row_term(pre[3 * i + 0], pre[3 * i + 1], pre[3 * i + 2], y[i], w);
    }

    // intra-block reduction
    #pragma unroll
    for (int off = 16; off > 0; off >>= 1)
        acc += __shfl_down_sync(0xFFFFFFFFu, acc, off);

    __shared__ float s[NTHREADS / 32];
    __shared__ bool s_last;
    int lane = threadIdx.x & 31;
    int wid  = threadIdx.x >> 5;
    if (lane == 0) s[wid] = acc;
    __syncthreads();

    if (wid == 0) {
        float v = (lane < NTHREADS / 32) ? s[lane] : 0.0f;
        #pragma unroll
        for (int off = 16; off > 0; off >>= 1)
            v += __shfl_down_sync(0xFFFFFFFFu, v, off);
        if (lane == 0) {
            g_partials[blockIdx.x] = v;
            __threadfence();
            unsigned int prev = atomicAdd(&g_done_count, 1u);
            s_last = (prev == (unsigned int)(gridDim.x - 1));
        }
    }
    __syncthreads();

    // last block to finish folds all partials (deterministic fixed order)
    if (s_last) {
        float v = 0.0f;
        #pragma unroll
        for (int k = threadIdx.x; k < NBLOCKS; k += NTHREADS)
            v += g_partials[k];

        #pragma unroll
        for (int off = 16; off > 0; off >>= 1)
            v += __shfl_down_sync(0xFFFFFFFFu, v, off);

        if (lane == 0) s[wid] = v;
        __syncthreads();
        if (wid == 0) {
            float t = (lane < NTHREADS / 32) ? s[lane] : 0.0f;
            #pragma unroll
            for (int off = 16; off > 0; off >>= 1)
                t += __shfl_down_sync(0xFFFFFFFFu, t, off);
            if (lane == 0) {
                out[0] = t * inv_n_neg;      // = -sum / N
                g_done_count = 0u;           // reset for next graph replay
            }
        }
    }
}

extern "C" void kernel_launch(void* const* d_in, const int* in_sizes, int n_in,
                              void* d_out, int out_size) {
    const float* pre = (const float*)d_in[0];
    const int*   y   = (const int*)d_in[1];
    const float* wp  = (const float*)d_in[2];
    float* out = (float*)d_out;

    const int n = in_sizes[1];   // y_true element count = number of rows

    nll_fused_kernel<<<NBLOCKS, NTHREADS>>>(pre, y, wp, out, n, -1.0f / (float)n);
}